// round 17
// baseline (speedup 1.0000x reference)
#include <cuda_runtime.h>

#define BB 4096
#define TT 2048
#define HH 10
#define SLOTF 964   // floats per ring slot: 10 warps * 96 + 4 pad (16B-aligned)

union F2U { float2 f; unsigned long long u; };

__device__ __forceinline__ float2 ffma2(float2 a, float2 b, float2 c) {
    F2U ua, ub, uc, ud;
    ua.f = a; ub.f = b; uc.f = c;
    asm("fma.rn.f32x2 %0, %1, %2, %3;" : "=l"(ud.u) : "l"(ua.u), "l"(ub.u), "l"(uc.u));
    return ud.f;
}
__device__ __forceinline__ float2 fmul2(float2 a, float2 b) {
    F2U ua, ub, ud;
    ua.f = a; ub.f = b;
    asm("mul.rn.f32x2 %0, %1, %2;" : "=l"(ud.u) : "l"(ua.u), "l"(ub.u));
    return ud.f;
}
__device__ __forceinline__ float2 fadd2(float2 a, float2 b) {
    F2U ua, ub, ud;
    ua.f = a; ub.f = b;
    asm("add.rn.f32x2 %0, %1, %2;" : "=l"(ud.u) : "l"(ua.u), "l"(ub.u));
    return ud.f;
}
__device__ __forceinline__ float tanh_fast(float x) {
    float y;
    asm("tanh.approx.f32 %0, %1;" : "=f"(y) : "f"(x));
    return y;
}

// One hidden unit per thread, 3 LSTM elements per warp (lanes 0..29).
// 10-warp CTAs, grid=137 -> <=1 CTA/SM, uniform 10 warps/SM.
// h stored DUPLICATED ((h,h) via one STS.64) in a 10-slot SMEM ring.
// Gate dots use TRANSPOSED PAIR-CHAINS: accumulator .x carries gate i, .y
// gate f (same for g/o) over the dup pairs -> no horizontal adds, no
// per-gate scalar inits: 30 FMA-pipe inst/step (was 35).
// Projection rotated across j-lanes (1 per 10 steps), reading the SAME dup
// layout via scalar FFMAs on .x halves -> no second layout needed.
// Activations MUFU.TANH (sigmoid 0.5-scale folded into weights/biases).
__global__ void __launch_bounds__(320, 1) lstm_fused_kernel(
    const float* __restrict__ x,      // [B, T, 1]
    const float* __restrict__ W_ih,   // [4H, 1]
    const float* __restrict__ W_hh,   // [4H, H]
    const float* __restrict__ b_ih,   // [4H]
    const float* __restrict__ b_hh,   // [4H]
    const float* __restrict__ W_out,  // [1, H]
    const float* __restrict__ b_out,  // [1]
    float* __restrict__ out)          // [B, T, 1]
{
    // flat ring: [slot][warp(10) x ew(4) x 24]
    __shared__ float ring[10 * SLOTF];

    const int tid  = threadIdx.x;
    const int lane = tid & 31;
    const int w    = tid >> 5;

    int ew = lane / HH;              // 0..2 element, 3 = idle lanes 30,31
    int j  = lane - ew * HH;         // hidden unit 0..9 (idle lanes: 0,1)
    const bool active = (ew < 3);

    int b = (blockIdx.x * 10 + w) * 3 + ew;
    const bool valid = active && (b < BB);
    const int bb = valid ? b : 0;

    // zero slot 9 of this warp's region (h[-1] = 0)
    for (int i = lane; i < 96; i += 32)
        ring[9 * SLOTF + w * 96 + i] = 0.0f;
    __syncwarp();

    // ---- per-thread constants (transposed gate pairs; sigmoid 0.5-scale folded) ----
    // wif[k] = (0.5*Wi[j][k], 0.5*Wf[j][k]); wgo[k] = (Wg[j][k], 0.5*Wo[j][k])
    float2 wif[HH], wgo[HH];
    float wo[HH];
#pragma unroll
    for (int k = 0; k < HH; k++) {
        wif[k] = make_float2(0.5f * W_hh[(0 * HH + j) * HH + k],
                             0.5f * W_hh[(1 * HH + j) * HH + k]);
        wgo[k] = make_float2(W_hh[(2 * HH + j) * HH + k],
                             0.5f * W_hh[(3 * HH + j) * HH + k]);
        wo[k] = W_out[k];
    }
    const float2 wxif = make_float2(0.5f * W_ih[0 * HH + j], 0.5f * W_ih[1 * HH + j]);
    const float2 wxgo = make_float2(       W_ih[2 * HH + j], 0.5f * W_ih[3 * HH + j]);
    const float2 bif  = make_float2(0.5f * (b_ih[0 * HH + j] + b_hh[0 * HH + j]),
                                    0.5f * (b_ih[1 * HH + j] + b_hh[1 * HH + j]));
    const float2 bgo  = make_float2(       (b_ih[2 * HH + j] + b_hh[2 * HH + j]),
                                    0.5f * (b_ih[3 * HH + j] + b_hh[3 * HH + j]));
    const float bout = b_out[0];

    const float* xp = x   + (size_t)bb * TT;
    float*       op = out + (size_t)bb * TT;

    // ring pointers: per-warp/element region = 24 floats per slot (dup pairs)
    const float* rg = ring + w * 96 + ew * 24;            // slot-0 gate-read base
    float*       wb = ring + w * 96 + ew * 24 + 2 * j;    // slot-0 write addr (STS.64)
    // projection: lane j reads slot (9-j); tail: lane j<8 reads slot (7-j)
    const float* pr  = ring + (9 - j) * SLOTF + w * 96 + ew * 24;
    const int st = (j < 8) ? (7 - j) : 0;
    const float* prt = ring + st * SLOTF + w * 96 + ew * 24;
    float* sp = op + (9 - j);    // per-lane output pointer

    float c = 0.0f;

    // One step: reads dup h[t-1] at rd, writes dup h[t] at wr.
    auto step = [&](float xv, const float* rd, float* wr) {
        float4 A = *(const float4*)rd;         // (h0,h0,h1,h1)
        float4 B = *(const float4*)(rd + 4);   // (h2,h2,h3,h3)
        float4 C = *(const float4*)(rd + 8);   // (h4,h4,h5,h5)
        float4 D = *(const float4*)(rd + 12);  // (h6,h6,h7,h7)
        float4 E = *(const float4*)(rd + 16);  // (h8,h8,h9,h9)
        float2 x2 = make_float2(xv, xv);

        // IF pair-chain: .x = gate i, .y = gate f
        float2 ifA = ffma2(x2, wxif, bif);
        ifA = ffma2(make_float2(A.x, A.y), wif[0], ifA);
        ifA = ffma2(make_float2(A.z, A.w), wif[1], ifA);
        ifA = ffma2(make_float2(B.x, B.y), wif[2], ifA);
        ifA = ffma2(make_float2(B.z, B.w), wif[3], ifA);
        ifA = ffma2(make_float2(C.x, C.y), wif[4], ifA);
        float2 ifB = fmul2(make_float2(C.z, C.w), wif[5]);
        ifB = ffma2(make_float2(D.x, D.y), wif[6], ifB);
        ifB = ffma2(make_float2(D.z, D.w), wif[7], ifB);
        ifB = ffma2(make_float2(E.x, E.y), wif[8], ifB);
        ifB = ffma2(make_float2(E.z, E.w), wif[9], ifB);
        float2 aIF = fadd2(ifA, ifB);

        // GO pair-chain: .x = gate g, .y = gate o
        float2 goA = ffma2(x2, wxgo, bgo);
        goA = ffma2(make_float2(A.x, A.y), wgo[0], goA);
        goA = ffma2(make_float2(A.z, A.w), wgo[1], goA);
        goA = ffma2(make_float2(B.x, B.y), wgo[2], goA);
        goA = ffma2(make_float2(B.z, B.w), wgo[3], goA);
        goA = ffma2(make_float2(C.x, C.y), wgo[4], goA);
        float2 goB = fmul2(make_float2(C.z, C.w), wgo[5]);
        goB = ffma2(make_float2(D.x, D.y), wgo[6], goB);
        goB = ffma2(make_float2(D.z, D.w), wgo[7], goB);
        goB = ffma2(make_float2(E.x, E.y), wgo[8], goB);
        goB = ffma2(make_float2(E.z, E.w), wgo[9], goB);
        float2 aGO = fadd2(goA, goB);

        float si = fmaf(tanh_fast(aIF.x), 0.5f, 0.5f);
        float sf = fmaf(tanh_fast(aIF.y), 0.5f, 0.5f);
        float g  =      tanh_fast(aGO.x);
        float so = fmaf(tanh_fast(aGO.y), 0.5f, 0.5f);
        c = fmaf(sf, c, si * g);
        float h = so * tanh_fast(c);
        *(float2*)wr = make_float2(h, h);   // STS.64; in-order per-warp SMEM pipe
    };

    // Projection from dup layout: scalar FFMAs on the .x halves.
    auto proj = [&](const float* p) -> float {
        float4 A = *(const float4*)p;
        float4 B = *(const float4*)(p + 4);
        float4 C = *(const float4*)(p + 8);
        float4 D = *(const float4*)(p + 12);
        float4 E = *(const float4*)(p + 16);
        float acc = fmaf(A.x, wo[0], bout);
        acc = fmaf(A.z, wo[1], acc);
        acc = fmaf(B.x, wo[2], acc);
        acc = fmaf(B.z, wo[3], acc);
        acc = fmaf(C.x, wo[4], acc);
        acc = fmaf(C.z, wo[5], acc);
        acc = fmaf(D.x, wo[6], acc);
        acc = fmaf(D.z, wo[7], acc);
        acc = fmaf(E.x, wo[8], acc);
        acc = fmaf(E.z, wo[9], acc);
        return acc;
    };

#define RD(s) (rg + (s) * SLOTF)
#define WRS(s) (wb + (s) * SLOTF)

    // ---- 102 blocks of 20 steps (t = 0..2039) ----
    float4 x4 = *(const float4*)xp;
    float4 xn4;
    for (int m = 0; m < 102; m++) {
        const float* xq = xp + 20 * m;
        float* spm = sp + 20 * m;
        xn4 = *(const float4*)(xq + 4);
        step(x4.x, RD(9), WRS(0));
        step(x4.y, RD(0), WRS(1));
        step(x4.z, RD(1), WRS(2));
        step(x4.w, RD(2), WRS(3));
        x4 = xn4; xn4 = *(const float4*)(xq + 8);
        step(x4.x, RD(3), WRS(4));
        step(x4.y, RD(4), WRS(5));
        step(x4.z, RD(5), WRS(6));
        step(x4.w, RD(6), WRS(7));
        x4 = xn4; xn4 = *(const float4*)(xq + 12);
        step(x4.x, RD(7), WRS(8));
        step(x4.y, RD(8), WRS(9));
        {   // projection point 1: out[20m .. 20m+9], lane j -> out[20m+9-j]
            float po = proj(pr);
            if (valid) spm[0] = po;
        }
        step(x4.z, RD(9), WRS(0));
        step(x4.w, RD(0), WRS(1));
        x4 = xn4; xn4 = *(const float4*)(xq + 16);
        step(x4.x, RD(1), WRS(2));
        step(x4.y, RD(2), WRS(3));
        step(x4.z, RD(3), WRS(4));
        step(x4.w, RD(4), WRS(5));
        x4 = xn4; xn4 = *(const float4*)(xq + 20);
        step(x4.x, RD(5), WRS(6));
        step(x4.y, RD(6), WRS(7));
        step(x4.z, RD(7), WRS(8));
        step(x4.w, RD(8), WRS(9));
        {   // projection point 2: out[20m+10 .. 20m+19]
            float po = proj(pr);
            if (valid) spm[10] = po;
        }
        x4 = xn4;
    }

    // ---- tail: t = 2040..2047 (x4 holds x[2040..2043]) ----
    xn4 = *(const float4*)(xp + 2044);
    step(x4.x, RD(9), WRS(0));
    step(x4.y, RD(0), WRS(1));
    step(x4.z, RD(1), WRS(2));
    step(x4.w, RD(2), WRS(3));
    x4 = xn4;
    step(x4.x, RD(3), WRS(4));
    step(x4.y, RD(4), WRS(5));
    step(x4.z, RD(5), WRS(6));
    step(x4.w, RD(6), WRS(7));
    {   // final projection: lanes j<8 -> out[2047-j] = sp[2038]
        float po = proj(prt);
        if (valid && j < 8) sp[2038] = po;
    }
#undef RD
#undef WRS
}

extern "C" void kernel_launch(void* const* d_in, const int* in_sizes, int n_in,
                              void* d_out, int out_size) {
    const float* x     = (const float*)d_in[0];
    const float* W_ih  = (const float*)d_in[1];
    const float* W_hh  = (const float*)d_in[2];
    const float* b_ih  = (const float*)d_in[3];
    const float* b_hh  = (const float*)d_in[4];
    const float* W_out = (const float*)d_in[5];
    const float* b_out = (const float*)d_in[6];
    float* out = (float*)d_out;

    // 10-warp CTAs, 30 elements each: 137 CTAs -> <=1 CTA/SM, uniform 10 warps/SM
    const int elems_per_block = 30;
    const int grid = (BB + elems_per_block - 1) / elems_per_block;  // 137
    lstm_fused_kernel<<<grid, 320>>>(x, W_ih, W_hh, b_ih, b_hh, W_out, b_out, out);
}